// round 1
// baseline (speedup 1.0000x reference)
#include <cuda_runtime.h>
#include <math.h>

#define B 1024
#define L 18
#define E 300
#define H 300
#define G4 1200   // 4H
#define X2E 600   // 2E
#define BL (B*L)  // 18432

// ---------------- scratch (allocation-free: __device__ globals) ----------------
__device__ float g_x [BL * X2E];        // x = concat(first, s)        44 MB
__device__ float g_ag[B * E];           // mean of sememe embeddings
__device__ float g_xg[2][BL * G4];      // xg for fwd/bwd              176 MB
__device__ float g_Vh[BL * 2 * H];      // concat(hf, hb)              44 MB
__device__ float g_h [2][2][B * H];     // ping-pong hidden state per dir
__device__ float g_c [2][B * H];        // cell state per dir

// ---------------- init ----------------
__global__ void zero_state_kernel() {
    int i = blockIdx.x * blockDim.x + threadIdx.x;
    if (i < 2 * 2 * B * H) (&g_h[0][0][0])[i] = 0.f;
    if (i < 2 * B * H)     (&g_c[0][0])[i]    = 0.f;
}

// ---------------- embedding gather + x build + mean ----------------
__global__ void embed_kernel(const int* __restrict__ word,
                             const int* __restrict__ sem,
                             const float* __restrict__ wt,
                             const float* __restrict__ st) {
    int b = blockIdx.x;
    int e = threadIdx.x;
    __shared__ int sidx[L];
    __shared__ int widx;
    if (e < L) sidx[e] = sem[b * L + e];
    if (e == 0) widx = word[b];
    __syncthreads();
    if (e < E) {
        float w = wt[widx * E + e];
        float acc = 0.f;
#pragma unroll
        for (int l = 0; l < L; l++) {
            int si = sidx[l];
            float s = st[si * E + e];
            acc += s;
            float* xr = g_x + (size_t)(b * L + l) * X2E;
            xr[e]     = (si == 0) ? s : w;   // first = where(sem==0, s, w)
            xr[E + e] = s;
        }
        g_ag[b * E + e] = acc * (1.f / (float)L);
    }
}

// ---------------- generic guarded SGEMM: C = A(MxK) @ W^T(NxK) + b1 + b2 [relu] ----------------
__global__ void __launch_bounds__(256)
sgemm_nt(const float* __restrict__ A, const float* __restrict__ W,
         const float* __restrict__ b1, const float* __restrict__ b2,
         float* __restrict__ C, int M, int N, int K, int dorelu) {
    __shared__ float As[8][128];
    __shared__ float Bs[8][128];
    int tid = threadIdx.x;
    int m0 = blockIdx.y * 128, n0 = blockIdx.x * 128;
    int ty = tid >> 4, tx = tid & 15;

    float acc[8][8];
#pragma unroll
    for (int r = 0; r < 8; r++)
#pragma unroll
        for (int c = 0; c < 8; c++) acc[r][c] = 0.f;

    for (int k0 = 0; k0 < K; k0 += 8) {
#pragma unroll
        for (int q = 0; q < 4; q++) {
            int e  = tid + q * 256;
            int mm = e >> 3, kk = e & 7;
            int gk = k0 + kk;
            int gm = m0 + mm;
            As[kk][mm] = (gm < M && gk < K) ? A[(size_t)gm * K + gk] : 0.f;
            int gn = n0 + mm;
            Bs[kk][mm] = (gn < N && gk < K) ? W[(size_t)gn * K + gk] : 0.f;
        }
        __syncthreads();
#pragma unroll
        for (int k = 0; k < 8; k++) {
            float a[8], bv[8];
#pragma unroll
            for (int r = 0; r < 8; r++) a[r] = As[k][ty * 8 + r];
#pragma unroll
            for (int c = 0; c < 8; c++) bv[c] = Bs[k][tx * 8 + c];
#pragma unroll
            for (int r = 0; r < 8; r++)
#pragma unroll
                for (int c = 0; c < 8; c++) acc[r][c] = fmaf(a[r], bv[c], acc[r][c]);
        }
        __syncthreads();
    }

#pragma unroll
    for (int r = 0; r < 8; r++) {
        int gm = m0 + ty * 8 + r;
        if (gm < M) {
#pragma unroll
            for (int c = 0; c < 8; c++) {
                int gn = n0 + tx * 8 + c;
                if (gn < N) {
                    float v = acc[r][c];
                    if (b1) v += b1[gn];
                    if (b2) v += b2[gn];
                    if (dorelu) v = fmaxf(v, 0.f);
                    C[(size_t)gm * N + gn] = v;
                }
            }
        }
    }
}

// ---------------- fused LSTM step: g = xg[:,t,:] + h @ Whh^T; gates; state update ----------------
// Tile: 64 batch x 32 j-cols x 4 gates. blockIdx.z = direction.
__global__ void __launch_bounds__(256)
lstm_step_kernel(int st,
                 const float* __restrict__ Whh_f,
                 const float* __restrict__ Whh_b) {
    const int KC = 20;
    int dir = blockIdx.z;
    const float* Whh   = dir ? Whh_b : Whh_f;
    const float* xg    = g_xg[dir];
    const float* hprev = g_h[dir][st & 1];
    float* hnext       = g_h[dir][(st + 1) & 1];
    float* cbuf        = g_c[dir];
    int t = dir ? (L - 1 - st) : st;

    __shared__ float sA[KC][64];       // h_prev tile, k-major
    __shared__ float sB[KC][4][32];    // Whh tile: [k][gate][j]

    int tid = threadIdx.x;
    int ty = tid >> 4, tx = tid & 15;  // ty: 4-batch group, tx: 2-j group
    int b0 = blockIdx.x * 64;
    int j0 = blockIdx.y * 32;

    float acc[4][4][2];                // [gate][batch][j]
#pragma unroll
    for (int g = 0; g < 4; g++)
#pragma unroll
        for (int i = 0; i < 4; i++) { acc[g][i][0] = 0.f; acc[g][i][1] = 0.f; }

    for (int k0 = 0; k0 < H; k0 += KC) {
        // load h_prev tile: 64*20 = 1280 elems
#pragma unroll
        for (int q = 0; q < 5; q++) {
            int e  = tid + q * 256;
            int bb = e / KC, kk = e - bb * KC;
            sA[kk][bb] = hprev[(b0 + bb) * H + k0 + kk];
        }
        // load Whh tile: 4*32*20 = 2560 elems
#pragma unroll
        for (int q = 0; q < 10; q++) {
            int e  = tid + q * 256;
            int kk = e % KC;
            int jj = (e / KC) & 31;
            int g  = e / (KC * 32);
            int gj = j0 + jj;
            sB[kk][g][jj] = (gj < H) ? Whh[(size_t)(g * H + gj) * H + k0 + kk] : 0.f;
        }
        __syncthreads();
#pragma unroll
        for (int k = 0; k < KC; k++) {
            float a0 = sA[k][ty * 4 + 0];
            float a1 = sA[k][ty * 4 + 1];
            float a2 = sA[k][ty * 4 + 2];
            float a3 = sA[k][ty * 4 + 3];
#pragma unroll
            for (int g = 0; g < 4; g++) {
                float w0 = sB[k][g][tx * 2 + 0];
                float w1 = sB[k][g][tx * 2 + 1];
                acc[g][0][0] = fmaf(a0, w0, acc[g][0][0]);
                acc[g][0][1] = fmaf(a0, w1, acc[g][0][1]);
                acc[g][1][0] = fmaf(a1, w0, acc[g][1][0]);
                acc[g][1][1] = fmaf(a1, w1, acc[g][1][1]);
                acc[g][2][0] = fmaf(a2, w0, acc[g][2][0]);
                acc[g][2][1] = fmaf(a2, w1, acc[g][2][1]);
                acc[g][3][0] = fmaf(a3, w0, acc[g][3][0]);
                acc[g][3][1] = fmaf(a3, w1, acc[g][3][1]);
            }
        }
        __syncthreads();
    }

    // epilogue: gates + state update
#pragma unroll
    for (int bi = 0; bi < 4; bi++) {
        int b   = b0 + ty * 4 + bi;
        int row = b * L + t;
        const float* xr = xg + (size_t)row * G4;
#pragma unroll
        for (int ji = 0; ji < 2; ji++) {
            int j = j0 + tx * 2 + ji;
            if (j < H) {
                float gi = acc[0][bi][ji] + xr[j];
                float gf = acc[1][bi][ji] + xr[H + j];
                float gg = acc[2][bi][ji] + xr[2 * H + j];
                float go = acc[3][bi][ji] + xr[3 * H + j];
                float ig = 1.f / (1.f + expf(-gi));
                float fg = 1.f / (1.f + expf(-gf));
                float gt = tanhf(gg);
                float og = 1.f / (1.f + expf(-go));
                float c  = fg * cbuf[b * H + j] + ig * gt;
                cbuf[b * H + j] = c;
                float h = og * tanhf(c);
                hnext[b * H + j] = h;
                g_Vh[(size_t)row * (2 * H) + dir * H + j] = h;
            }
        }
    }
}

// ---------------- launch ----------------
extern "C" void kernel_launch(void* const* d_in, const int* in_sizes, int n_in,
                              void* d_out, int out_size) {
    const int*   word  = (const int*)d_in[0];
    const int*   sem   = (const int*)d_in[1];
    const float* wt    = (const float*)d_in[2];
    const float* st    = (const float*)d_in[3];
    const float* Wih_f = (const float*)d_in[4];
    const float* Whh_f = (const float*)d_in[5];
    const float* bih_f = (const float*)d_in[6];
    const float* bhh_f = (const float*)d_in[7];
    const float* Wih_b = (const float*)d_in[8];
    const float* Whh_b = (const float*)d_in[9];
    const float* bih_b = (const float*)d_in[10];
    const float* bhh_b = (const float*)d_in[11];
    const float* Wa    = (const float*)d_in[12];
    const float* ba    = (const float*)d_in[13];
    const float* Wb    = (const float*)d_in[14];
    const float* bb    = (const float*)d_in[15];

    float* out    = (float*)d_out;
    float* Vout   = out;                          // (B, L, H)
    float* vg_out = out + (size_t)B * L * H;      // (B, E)

    // scratch pointers (cudaGetSymbolAddress is not a stream op — capture-safe)
    void* p;
    float *px, *pag, *pxgf, *pxgb, *pvh;
    cudaGetSymbolAddress(&p, g_x);  px  = (float*)p;
    cudaGetSymbolAddress(&p, g_ag); pag = (float*)p;
    cudaGetSymbolAddress(&p, g_xg); pxgf = (float*)p; pxgb = pxgf + (size_t)BL * G4;
    cudaGetSymbolAddress(&p, g_Vh); pvh = (float*)p;

    zero_state_kernel<<<(2 * 2 * B * H + 255) / 256, 256>>>();
    embed_kernel<<<B, 320>>>(word, sem, wt, st);

    // v_g = relu(a_g @ Wb^T + bb)
    sgemm_nt<<<dim3((E + 127) / 128, (B + 127) / 128), 256>>>(
        pag, Wb, bb, nullptr, vg_out, B, E, E, 1);

    // xg_d = x @ Wih_d^T + bih_d + bhh_d
    sgemm_nt<<<dim3((G4 + 127) / 128, (BL + 127) / 128), 256>>>(
        px, Wih_f, bih_f, bhh_f, pxgf, BL, G4, X2E, 0);
    sgemm_nt<<<dim3((G4 + 127) / 128, (BL + 127) / 128), 256>>>(
        px, Wih_b, bih_b, bhh_b, pxgb, BL, G4, X2E, 0);

    // recurrence: 18 steps, both directions per launch
    for (int s = 0; s < L; s++)
        lstm_step_kernel<<<dim3(16, 10, 2), 256>>>(s, Whh_f, Whh_b);

    // V = relu(Vh @ Wa^T + ba)
    sgemm_nt<<<dim3((H + 127) / 128, (BL + 127) / 128), 256>>>(
        pvh, Wa, ba, nullptr, Vout, BL, H, 2 * H, 1);
}

// round 2
// speedup vs baseline: 1.3729x; 1.3729x over previous
#include <cuda_runtime.h>
#include <math.h>

#define B 1024
#define L 18
#define E 300
#define H 300
#define G4 1200   // 4H
#define VS 2186
#define BL (B*L)  // 18432

// ---------------- scratch (allocation-free: __device__ globals) ----------------
__device__ float g_ag[B * E];            // mean of sememe embeddings
__device__ float g_w [B * E];            // gathered word embeddings
__device__ float g_sproj[2][VS * G4];    // sem_table @ Wih_s^T + bih + bhh   (per dir) 21 MB
__device__ float g_wproj[2][B * G4];     // w @ Wih_first^T                    (per dir) 10 MB
__device__ float g_Vh[BL * 2 * H];       // concat(hf, hb)                     44 MB
__device__ float g_h [2][2][B * H];      // ping-pong hidden state per dir
__device__ float g_c [2][B * H];         // cell state per dir

// ---------------- init ----------------
__global__ void zero_state_kernel() {
    int i = blockIdx.x * blockDim.x + threadIdx.x;
    if (i < 2 * 2 * B * H) (&g_h[0][0][0])[i] = 0.f;
    if (i < 2 * B * H)     (&g_c[0][0])[i]    = 0.f;
}

// ---------------- embedding gather: a_g (mean) + word embedding ----------------
__global__ void embed_kernel(const int* __restrict__ word,
                             const int* __restrict__ sem,
                             const float* __restrict__ wt,
                             const float* __restrict__ st) {
    int b = blockIdx.x;
    int e = threadIdx.x;
    __shared__ int sidx[L];
    __shared__ int widx;
    if (e < L) sidx[e] = sem[b * L + e];
    if (e == 0) widx = word[b];
    __syncthreads();
    if (e < E) {
        float acc = 0.f;
#pragma unroll
        for (int l = 0; l < L; l++) acc += st[sidx[l] * E + e];
        g_ag[b * E + e] = acc * (1.f / (float)L);
        g_w [b * E + e] = wt[widx * E + e];
    }
}

// ---------------- generic guarded SGEMM: C = A(MxK,lda) @ W^T(NxK,ldw) + b1 + b2 [relu] ----------------
__global__ void __launch_bounds__(256)
sgemm_nt(const float* __restrict__ A, int lda,
         const float* __restrict__ W, int ldw,
         const float* __restrict__ b1, const float* __restrict__ b2,
         float* __restrict__ C, int M, int N, int K, int dorelu) {
    __shared__ float As[8][128];
    __shared__ float Bs[8][128];
    int tid = threadIdx.x;
    int m0 = blockIdx.y * 128, n0 = blockIdx.x * 128;
    int ty = tid >> 4, tx = tid & 15;

    float acc[8][8];
#pragma unroll
    for (int r = 0; r < 8; r++)
#pragma unroll
        for (int c = 0; c < 8; c++) acc[r][c] = 0.f;

    for (int k0 = 0; k0 < K; k0 += 8) {
#pragma unroll
        for (int q = 0; q < 4; q++) {
            int e  = tid + q * 256;
            int mm = e >> 3, kk = e & 7;
            int gk = k0 + kk;
            int gm = m0 + mm;
            As[kk][mm] = (gm < M && gk < K) ? A[(size_t)gm * lda + gk] : 0.f;
            int gn = n0 + mm;
            Bs[kk][mm] = (gn < N && gk < K) ? W[(size_t)gn * ldw + gk] : 0.f;
        }
        __syncthreads();
#pragma unroll
        for (int k = 0; k < 8; k++) {
            float4 a0 = *(const float4*)&As[k][ty * 8];
            float4 a1 = *(const float4*)&As[k][ty * 8 + 4];
            float4 w0 = *(const float4*)&Bs[k][tx * 8];
            float4 w1 = *(const float4*)&Bs[k][tx * 8 + 4];
            float a[8] = {a0.x, a0.y, a0.z, a0.w, a1.x, a1.y, a1.z, a1.w};
            float bv[8] = {w0.x, w0.y, w0.z, w0.w, w1.x, w1.y, w1.z, w1.w};
#pragma unroll
            for (int r = 0; r < 8; r++)
#pragma unroll
                for (int c = 0; c < 8; c++) acc[r][c] = fmaf(a[r], bv[c], acc[r][c]);
        }
        __syncthreads();
    }

#pragma unroll
    for (int r = 0; r < 8; r++) {
        int gm = m0 + ty * 8 + r;
        if (gm < M) {
#pragma unroll
            for (int c = 0; c < 8; c++) {
                int gn = n0 + tx * 8 + c;
                if (gn < N) {
                    float v = acc[r][c];
                    if (b1) v += b1[gn];
                    if (b2) v += b2[gn];
                    if (dorelu) v = fmaxf(v, 0.f);
                    C[(size_t)gm * N + gn] = v;
                }
            }
        }
    }
}

// ---------------- fused LSTM step ----------------
// g = s_proj[sem[b,t]] + (sem!=0)*w_proj[b] + h_prev @ Whh^T ; gates; state update.
// Tile: 64 batch x (4 gates x 32 j). blockIdx.z = direction.
__global__ void __launch_bounds__(256)
lstm_step_kernel(int st,
                 const float* __restrict__ Whh_f,
                 const float* __restrict__ Whh_b,
                 const int* __restrict__ sem) {
    const int KC = 20;
    int dir = blockIdx.z;
    const float* Whh   = dir ? Whh_b : Whh_f;
    const float* sproj = g_sproj[dir];
    const float* wproj = g_wproj[dir];
    const float* hprev = g_h[dir][st & 1];
    float* hnext       = g_h[dir][(st + 1) & 1];
    float* cbuf        = g_c[dir];
    int t = dir ? (L - 1 - st) : st;

    __shared__ float sA[KC][64];       // h_prev tile, k-major (batch contiguous)
    __shared__ float sB[KC][4][32];    // Whh tile: [k][gate][j]

    int tid = threadIdx.x;
    int ty = tid >> 4, tx = tid & 15;  // ty: 4-batch group, tx: 2-j group
    int b0 = blockIdx.x * 64;
    int j0 = blockIdx.y * 32;

    float acc[4][4][2];                // [gate][batch][j]
#pragma unroll
    for (int g = 0; g < 4; g++)
#pragma unroll
        for (int i = 0; i < 4; i++) { acc[g][i][0] = 0.f; acc[g][i][1] = 0.f; }

    for (int k0 = 0; k0 < H; k0 += KC) {
        // load h_prev tile: 64*20 = 1280 elems
#pragma unroll
        for (int q = 0; q < 5; q++) {
            int e  = tid + q * 256;
            int bb = e / KC, kk = e - bb * KC;
            sA[kk][bb] = hprev[(b0 + bb) * H + k0 + kk];
        }
        // load Whh tile: 4*32*20 = 2560 elems
#pragma unroll
        for (int q = 0; q < 10; q++) {
            int e  = tid + q * 256;
            int kk = e % KC;
            int jj = (e / KC) & 31;
            int g  = e / (KC * 32);
            int gj = j0 + jj;
            sB[kk][g][jj] = (gj < H) ? Whh[(size_t)(g * H + gj) * H + k0 + kk] : 0.f;
        }
        __syncthreads();
#pragma unroll
        for (int k = 0; k < KC; k++) {
            float4 av = *(const float4*)&sA[k][ty * 4];
            float a[4] = {av.x, av.y, av.z, av.w};
#pragma unroll
            for (int g = 0; g < 4; g++) {
                float2 wv = *(const float2*)&sB[k][g][tx * 2];
#pragma unroll
                for (int i = 0; i < 4; i++) {
                    acc[g][i][0] = fmaf(a[i], wv.x, acc[g][i][0]);
                    acc[g][i][1] = fmaf(a[i], wv.y, acc[g][i][1]);
                }
            }
        }
        __syncthreads();
    }

    // epilogue: add gathered xg contributions, gates, state update
#pragma unroll
    for (int bi = 0; bi < 4; bi++) {
        int b   = b0 + ty * 4 + bi;
        int row = b * L + t;
        int idx = sem[row];
        const float* sp = sproj + (size_t)idx * G4;
        const float* wp = wproj + (size_t)b * G4;
        float wmul = (idx != 0) ? 1.f : 0.f;
#pragma unroll
        for (int ji = 0; ji < 2; ji++) {
            int j = j0 + tx * 2 + ji;
            if (j < H) {
                float gi = acc[0][bi][ji] + sp[j]         + wmul * wp[j];
                float gf = acc[1][bi][ji] + sp[H + j]     + wmul * wp[H + j];
                float gg = acc[2][bi][ji] + sp[2 * H + j] + wmul * wp[2 * H + j];
                float go = acc[3][bi][ji] + sp[3 * H + j] + wmul * wp[3 * H + j];
                float ig = 1.f / (1.f + expf(-gi));
                float fg = 1.f / (1.f + expf(-gf));
                float gt = tanhf(gg);
                float og = 1.f / (1.f + expf(-go));
                float c  = fg * cbuf[b * H + j] + ig * gt;
                cbuf[b * H + j] = c;
                float h = og * tanhf(c);
                hnext[b * H + j] = h;
                g_Vh[(size_t)row * (2 * H) + dir * H + j] = h;
            }
        }
    }
}

// ---------------- launch ----------------
extern "C" void kernel_launch(void* const* d_in, const int* in_sizes, int n_in,
                              void* d_out, int out_size) {
    const int*   word  = (const int*)d_in[0];
    const int*   sem   = (const int*)d_in[1];
    const float* wt    = (const float*)d_in[2];
    const float* st    = (const float*)d_in[3];
    const float* Wih_f = (const float*)d_in[4];
    const float* Whh_f = (const float*)d_in[5];
    const float* bih_f = (const float*)d_in[6];
    const float* bhh_f = (const float*)d_in[7];
    const float* Wih_b = (const float*)d_in[8];
    const float* Whh_b = (const float*)d_in[9];
    const float* bih_b = (const float*)d_in[10];
    const float* bhh_b = (const float*)d_in[11];
    const float* Wa    = (const float*)d_in[12];
    const float* ba    = (const float*)d_in[13];
    const float* Wb    = (const float*)d_in[14];
    const float* bb    = (const float*)d_in[15];

    float* out    = (float*)d_out;
    float* Vout   = out;                          // (B, L, H)
    float* vg_out = out + (size_t)B * L * H;      // (B, E)

    void* p;
    float *pag, *pw, *psf, *psb, *pwf, *pwb, *pvh;
    cudaGetSymbolAddress(&p, g_ag);    pag = (float*)p;
    cudaGetSymbolAddress(&p, g_w);     pw  = (float*)p;
    cudaGetSymbolAddress(&p, g_sproj); psf = (float*)p; psb = psf + (size_t)VS * G4;
    cudaGetSymbolAddress(&p, g_wproj); pwf = (float*)p; pwb = pwf + (size_t)B * G4;
    cudaGetSymbolAddress(&p, g_Vh);    pvh = (float*)p;

    zero_state_kernel<<<(2 * 2 * B * H + 255) / 256, 256>>>();
    embed_kernel<<<B, 320>>>(word, sem, wt, st);

    // v_g = relu(a_g @ Wb^T + bb)
    sgemm_nt<<<dim3((E + 127) / 128, (B + 127) / 128), 256>>>(
        pag, E, Wb, E, bb, nullptr, vg_out, B, E, E, 1);

    // s_proj_d = sem_table @ Wih_d[:,300:]^T + bih_d + bhh_d   (VS x 1200)
    sgemm_nt<<<dim3((G4 + 127) / 128, (VS + 127) / 128), 256>>>(
        st, E, Wih_f + E, 2 * E, bih_f, bhh_f, psf, VS, G4, E, 0);
    sgemm_nt<<<dim3((G4 + 127) / 128, (VS + 127) / 128), 256>>>(
        st, E, Wih_b + E, 2 * E, bih_b, bhh_b, psb, VS, G4, E, 0);

    // w_proj_d = w @ Wih_d[:,:300]^T    (B x 1200)
    sgemm_nt<<<dim3((G4 + 127) / 128, (B + 127) / 128), 256>>>(
        pw, E, Wih_f, 2 * E, nullptr, nullptr, pwf, B, G4, E, 0);
    sgemm_nt<<<dim3((G4 + 127) / 128, (B + 127) / 128), 256>>>(
        pw, E, Wih_b, 2 * E, nullptr, nullptr, pwb, B, G4, E, 0);

    // recurrence: 18 steps, both directions per launch
    for (int s = 0; s < L; s++)
        lstm_step_kernel<<<dim3(16, 10, 2), 256>>>(s, Whh_f, Whh_b, sem);

    // V = relu(Vh @ Wa^T + ba)
    sgemm_nt<<<dim3((H + 127) / 128, (BL + 127) / 128), 256>>>(
        pvh, 2 * H, Wa, 2 * H, ba, nullptr, Vout, BL, H, 2 * H, 1);
}

// round 3
// speedup vs baseline: 2.6092x; 1.9005x over previous
#include <cuda_runtime.h>
#include <math.h>

#define B 1024
#define L 18
#define E 300
#define H 300
#define G4 1200   // 4H
#define VS 2186
#define BL (B*L)  // 18432

// ---------------- scratch (allocation-free: __device__ globals) ----------------
__device__ float g_ag[B * E];            // mean of sememe embeddings
__device__ float g_w [B * E];            // gathered word embeddings
__device__ float g_sproj[2][VS * G4];    // sem_table @ Wih_s^T + bih + bhh (per dir)
__device__ float g_wproj[2][B * G4];     // w @ Wih_first^T (per dir)
__device__ float g_Vh[BL * 2 * H];       // concat(hf, hb)
__device__ float g_hT[2][2][H * B];      // ping-pong hidden state, [j][b] layout
__device__ float g_c [2][B * H];         // cell state, [b][j] layout
__device__ float g_WhhT[2][H * G4];      // Whh transposed: [k][g*H+j]

// ---------------- init ----------------
__global__ void zero_state_kernel() {
    int i = blockIdx.x * blockDim.x + threadIdx.x;
    if (i < 2 * 2 * H * B) (&g_hT[0][0][0])[i] = 0.f;
    if (i < 2 * B * H)     (&g_c[0][0])[i]     = 0.f;
}

// ---------------- Whh transpose: W[1200][300] -> WT[300][1200] ----------------
__global__ void transpose_whh(const float* __restrict__ Wf,
                              const float* __restrict__ Wb) {
    __shared__ float ts[32][33];
    int dir = blockIdx.z;
    const float* W = dir ? Wb : Wf;
    int c0 = blockIdx.x * 32;   // k (0..300)
    int r0 = blockIdx.y * 32;   // gj (0..1200)
    int x = threadIdx.x, y = threadIdx.y;  // 32 x 8
#pragma unroll
    for (int i = y; i < 32; i += 8) {
        int r = r0 + i, c = c0 + x;
        ts[i][x] = (r < G4 && c < H) ? W[(size_t)r * H + c] : 0.f;
    }
    __syncthreads();
#pragma unroll
    for (int i = y; i < 32; i += 8) {
        int r = c0 + i, c = r0 + x;   // r: k, c: gj
        if (r < H && c < G4) g_WhhT[dir][(size_t)r * G4 + c] = ts[x][i];
    }
}

// ---------------- embedding gather: a_g (mean) + word embedding ----------------
__global__ void embed_kernel(const int* __restrict__ word,
                             const int* __restrict__ sem,
                             const float* __restrict__ wt,
                             const float* __restrict__ st) {
    int b = blockIdx.x;
    int e = threadIdx.x;
    __shared__ int sidx[L];
    __shared__ int widx;
    if (e < L) sidx[e] = sem[b * L + e];
    if (e == 0) widx = word[b];
    __syncthreads();
    if (e < E) {
        float acc = 0.f;
#pragma unroll
        for (int l = 0; l < L; l++) acc += st[sidx[l] * E + e];
        g_ag[b * E + e] = acc * (1.f / (float)L);
        g_w [b * E + e] = wt[widx * E + e];
    }
}

// ---------------- double-buffered guarded SGEMM ----------------
// C = A(MxK,lda) @ W^T(NxK,ldw) + b1 + b2 [relu]; blockIdx.z selects pointer set.
__global__ void __launch_bounds__(256)
sgemm_nt(const float* __restrict__ A0, const float* __restrict__ A1, int lda,
         const float* __restrict__ W0, const float* __restrict__ W1, int ldw,
         const float* __restrict__ b10, const float* __restrict__ b11,
         const float* __restrict__ b20, const float* __restrict__ b21,
         float* __restrict__ C0, float* __restrict__ C1,
         int M, int N, int K, int dorelu) {
    int z = blockIdx.z;
    const float* A  = z ? A1 : A0;
    const float* W  = z ? W1 : W0;
    const float* b1 = z ? b11 : b10;
    const float* b2 = z ? b21 : b20;
    float* C        = z ? C1 : C0;

    __shared__ float As[2][8][128];
    __shared__ float Bs[2][8][128];
    int tid = threadIdx.x;
    int m0 = blockIdx.y * 128, n0 = blockIdx.x * 128;
    int ty = tid >> 4, tx = tid & 15;

    float acc[8][8];
#pragma unroll
    for (int r = 0; r < 8; r++)
#pragma unroll
        for (int c = 0; c < 8; c++) acc[r][c] = 0.f;

    int NC = (K + 7) / 8;
    float pa[4], pb[4];

    // prefetch chunk 0
#pragma unroll
    for (int q = 0; q < 4; q++) {
        int e = tid + q * 256;
        int mm = e >> 3, kk = e & 7;
        int gm = m0 + mm, gn = n0 + mm;
        pa[q] = (gm < M && kk < K) ? A[(size_t)gm * lda + kk] : 0.f;
        pb[q] = (gn < N && kk < K) ? W[(size_t)gn * ldw + kk] : 0.f;
    }
#pragma unroll
    for (int q = 0; q < 4; q++) {
        int e = tid + q * 256;
        int mm = e >> 3, kk = e & 7;
        As[0][kk][mm] = pa[q];
        Bs[0][kk][mm] = pb[q];
    }
    __syncthreads();

    for (int kc = 0; kc < NC; kc++) {
        int cur = kc & 1;
        if (kc + 1 < NC) {
            int k0 = (kc + 1) * 8;
#pragma unroll
            for (int q = 0; q < 4; q++) {
                int e = tid + q * 256;
                int mm = e >> 3, kk = e & 7;
                int gk = k0 + kk;
                int gm = m0 + mm, gn = n0 + mm;
                pa[q] = (gm < M && gk < K) ? A[(size_t)gm * lda + gk] : 0.f;
                pb[q] = (gn < N && gk < K) ? W[(size_t)gn * ldw + gk] : 0.f;
            }
        }
#pragma unroll
        for (int k = 0; k < 8; k++) {
            float4 a0 = *(const float4*)&As[cur][k][ty * 8];
            float4 a1 = *(const float4*)&As[cur][k][ty * 8 + 4];
            float4 w0 = *(const float4*)&Bs[cur][k][tx * 8];
            float4 w1 = *(const float4*)&Bs[cur][k][tx * 8 + 4];
            float a[8] = {a0.x, a0.y, a0.z, a0.w, a1.x, a1.y, a1.z, a1.w};
            float bv[8] = {w0.x, w0.y, w0.z, w0.w, w1.x, w1.y, w1.z, w1.w};
#pragma unroll
            for (int r = 0; r < 8; r++)
#pragma unroll
                for (int c = 0; c < 8; c++) acc[r][c] = fmaf(a[r], bv[c], acc[r][c]);
        }
        if (kc + 1 < NC) {
            int nxt = cur ^ 1;
#pragma unroll
            for (int q = 0; q < 4; q++) {
                int e = tid + q * 256;
                int mm = e >> 3, kk = e & 7;
                As[nxt][kk][mm] = pa[q];
                Bs[nxt][kk][mm] = pb[q];
            }
        }
        __syncthreads();
    }

#pragma unroll
    for (int r = 0; r < 8; r++) {
        int gm = m0 + ty * 8 + r;
        if (gm < M) {
#pragma unroll
            for (int c = 0; c < 8; c++) {
                int gn = n0 + tx * 8 + c;
                if (gn < N) {
                    float v = acc[r][c];
                    if (b1) v += b1[gn];
                    if (b2) v += b2[gn];
                    if (dorelu) v = fmaxf(v, 0.f);
                    C[(size_t)gm * N + gn] = v;
                }
            }
        }
    }
}

// ---------------- fused LSTM step v3 ----------------
// g = s_proj[sem[b,t]] + (sem!=0)*w_proj[b] + h_prev @ Whh^T ; gates; state update.
// Tile: 128 batch x 36 j x 4 gates, 288 threads, double-buffered, one wave (144 blocks).
#define KC 20
#define NCH (H / KC)   // 15
__global__ void __launch_bounds__(288)
lstm_step_kernel(int st, const int* __restrict__ sem) {
    int dir = blockIdx.z;
    const float* WT    = g_WhhT[dir];
    const float* sproj = g_sproj[dir];
    const float* wproj = g_wproj[dir];
    const float* hprevT = g_hT[dir][st & 1];
    float* hnextT       = g_hT[dir][(st + 1) & 1];
    float* cbuf         = g_c[dir];
    int t = dir ? (L - 1 - st) : st;

    __shared__ float sA[2][KC][128];    // h_prev tile [k][b]
    __shared__ float sB[2][KC][144];    // WhhT tile [k][g*36+jj]

    int tid = threadIdx.x;
    int ty = tid / 18, tx = tid - ty * 18;   // ty: 8-batch group (0..15), tx: 2-j group (0..17)
    int b0 = blockIdx.x * 128;
    int j0 = blockIdx.y * 36;

    float acc[4][8][2];
#pragma unroll
    for (int g = 0; g < 4; g++)
#pragma unroll
        for (int i = 0; i < 8; i++) { acc[g][i][0] = 0.f; acc[g][i][1] = 0.f; }

    float ra[9], rb[10];

    // prefetch chunk 0
#pragma unroll
    for (int q = 0; q < 9; q++) {
        int e = tid + q * 288;
        ra[q] = (e < KC * 128) ? hprevT[(size_t)(e >> 7) * B + b0 + (e & 127)] : 0.f;
    }
#pragma unroll
    for (int q = 0; q < 10; q++) {
        int e = tid + q * 288;
        int col = e % 144, kk = e / 144;
        int g = col / 36, jj = col - g * 36;
        int gj = j0 + jj;
        rb[q] = (gj < H) ? WT[(size_t)kk * G4 + g * H + gj] : 0.f;
    }
#pragma unroll
    for (int q = 0; q < 9; q++) {
        int e = tid + q * 288;
        if (e < KC * 128) sA[0][e >> 7][e & 127] = ra[q];
    }
#pragma unroll
    for (int q = 0; q < 10; q++) {
        int e = tid + q * 288;
        sB[0][e / 144][e % 144] = rb[q];
    }
    __syncthreads();

    for (int kc = 0; kc < NCH; kc++) {
        int cur = kc & 1;
        if (kc + 1 < NCH) {
            int k0 = (kc + 1) * KC;
#pragma unroll
            for (int q = 0; q < 9; q++) {
                int e = tid + q * 288;
                ra[q] = (e < KC * 128) ? hprevT[(size_t)(k0 + (e >> 7)) * B + b0 + (e & 127)] : 0.f;
            }
#pragma unroll
            for (int q = 0; q < 10; q++) {
                int e = tid + q * 288;
                int col = e % 144, kk = e / 144;
                int g = col / 36, jj = col - g * 36;
                int gj = j0 + jj;
                rb[q] = (gj < H) ? WT[(size_t)(k0 + kk) * G4 + g * H + gj] : 0.f;
            }
        }
#pragma unroll
        for (int k = 0; k < KC; k++) {
            float4 a0 = *(const float4*)&sA[cur][k][ty * 8];
            float4 a1 = *(const float4*)&sA[cur][k][ty * 8 + 4];
            float a[8] = {a0.x, a0.y, a0.z, a0.w, a1.x, a1.y, a1.z, a1.w};
#pragma unroll
            for (int g = 0; g < 4; g++) {
                float2 wv = *(const float2*)&sB[cur][k][g * 36 + tx * 2];
#pragma unroll
                for (int i = 0; i < 8; i++) {
                    acc[g][i][0] = fmaf(a[i], wv.x, acc[g][i][0]);
                    acc[g][i][1] = fmaf(a[i], wv.y, acc[g][i][1]);
                }
            }
        }
        if (kc + 1 < NCH) {
            int nxt = cur ^ 1;
#pragma unroll
            for (int q = 0; q < 9; q++) {
                int e = tid + q * 288;
                if (e < KC * 128) sA[nxt][e >> 7][e & 127] = ra[q];
            }
#pragma unroll
            for (int q = 0; q < 10; q++) {
                int e = tid + q * 288;
                sB[nxt][e / 144][e % 144] = rb[q];
            }
        }
        __syncthreads();
    }

    // epilogue
    int j = j0 + tx * 2;
    if (j < H) {
#pragma unroll
        for (int bi = 0; bi < 8; bi++) {
            int b   = b0 + ty * 8 + bi;
            int row = b * L + t;
            int idx = sem[row];
            const float* sp = sproj + (size_t)idx * G4;
            const float* wp = wproj + (size_t)b * G4;
            float wm = (idx != 0) ? 1.f : 0.f;

            float2 s0 = *(const float2*)(sp + j);
            float2 s1 = *(const float2*)(sp + H + j);
            float2 s2 = *(const float2*)(sp + 2 * H + j);
            float2 s3 = *(const float2*)(sp + 3 * H + j);
            float2 w0 = *(const float2*)(wp + j);
            float2 w1 = *(const float2*)(wp + H + j);
            float2 w2 = *(const float2*)(wp + 2 * H + j);
            float2 w3 = *(const float2*)(wp + 3 * H + j);
            float2 cv = *(const float2*)(cbuf + (size_t)b * H + j);

            float2 hv, cn;
#pragma unroll
            for (int ji = 0; ji < 2; ji++) {
                float gi = acc[0][bi][ji] + (ji ? s0.y : s0.x) + wm * (ji ? w0.y : w0.x);
                float gf = acc[1][bi][ji] + (ji ? s1.y : s1.x) + wm * (ji ? w1.y : w1.x);
                float gg = acc[2][bi][ji] + (ji ? s2.y : s2.x) + wm * (ji ? w2.y : w2.x);
                float go = acc[3][bi][ji] + (ji ? s3.y : s3.x) + wm * (ji ? w3.y : w3.x);
                float ig = 1.f / (1.f + expf(-gi));
                float fg = 1.f / (1.f + expf(-gf));
                float gt = tanhf(gg);
                float og = 1.f / (1.f + expf(-go));
                float c  = fg * (ji ? cv.y : cv.x) + ig * gt;
                float h  = og * tanhf(c);
                if (ji) { cn.y = c; hv.y = h; } else { cn.x = c; hv.x = h; }
            }
            *(float2*)(cbuf + (size_t)b * H + j) = cn;
            *(float2*)(g_Vh + (size_t)row * (2 * H) + dir * H + j) = hv;
            hnextT[(size_t)j * B + b]       = hv.x;
            hnextT[(size_t)(j + 1) * B + b] = hv.y;
        }
    }
}

// ---------------- launch ----------------
extern "C" void kernel_launch(void* const* d_in, const int* in_sizes, int n_in,
                              void* d_out, int out_size) {
    const int*   word  = (const int*)d_in[0];
    const int*   sem   = (const int*)d_in[1];
    const float* wt    = (const float*)d_in[2];
    const float* st    = (const float*)d_in[3];
    const float* Wih_f = (const float*)d_in[4];
    const float* Whh_f = (const float*)d_in[5];
    const float* bih_f = (const float*)d_in[6];
    const float* bhh_f = (const float*)d_in[7];
    const float* Wih_b = (const float*)d_in[8];
    const float* Whh_b = (const float*)d_in[9];
    const float* bih_b = (const float*)d_in[10];
    const float* bhh_b = (const float*)d_in[11];
    const float* Wa    = (const float*)d_in[12];
    const float* ba    = (const float*)d_in[13];
    const float* Wb    = (const float*)d_in[14];
    const float* bb    = (const float*)d_in[15];

    float* out    = (float*)d_out;
    float* Vout   = out;                          // (B, L, H)
    float* vg_out = out + (size_t)B * L * H;      // (B, E)

    void* p;
    float *pag, *pw, *psf, *psb, *pwf, *pwb, *pvh;
    cudaGetSymbolAddress(&p, g_ag);    pag = (float*)p;
    cudaGetSymbolAddress(&p, g_w);     pw  = (float*)p;
    cudaGetSymbolAddress(&p, g_sproj); psf = (float*)p; psb = psf + (size_t)VS * G4;
    cudaGetSymbolAddress(&p, g_wproj); pwf = (float*)p; pwb = pwf + (size_t)B * G4;
    cudaGetSymbolAddress(&p, g_Vh);    pvh = (float*)p;

    zero_state_kernel<<<(2 * 2 * B * H + 255) / 256, 256>>>();
    transpose_whh<<<dim3(10, 38, 2), dim3(32, 8)>>>(Whh_f, Whh_b);
    embed_kernel<<<B, 320>>>(word, sem, wt, st);

    // v_g = relu(a_g @ Wb^T + bb)
    sgemm_nt<<<dim3(3, 8, 1), 256>>>(
        pag, pag, E, Wb, Wb, E, bb, bb, nullptr, nullptr,
        vg_out, vg_out, B, E, E, 1);

    // s_proj_d = sem_table @ Wih_d[:,300:]^T + bih_d + bhh_d   (VS x 1200)
    sgemm_nt<<<dim3(10, 18, 2), 256>>>(
        st, st, E, Wih_f + E, Wih_b + E, 2 * E, bih_f, bih_b, bhh_f, bhh_b,
        psf, psb, VS, G4, E, 0);

    // w_proj_d = w @ Wih_d[:,:300]^T    (B x 1200)
    sgemm_nt<<<dim3(10, 8, 2), 256>>>(
        pw, pw, E, Wih_f, Wih_b, 2 * E, nullptr, nullptr, nullptr, nullptr,
        pwf, pwb, B, G4, E, 0);

    // recurrence: 18 steps, both directions per launch
    for (int s = 0; s < L; s++)
        lstm_step_kernel<<<dim3(8, 9, 2), 288>>>(s, sem);

    // V = relu(Vh @ Wa^T + ba)
    sgemm_nt<<<dim3(3, 144, 1), 256>>>(
        pvh, pvh, 2 * H, Wa, Wa, 2 * H, ba, ba, nullptr, nullptr,
        Vout, Vout, BL, H, 2 * H, 1);
}